// round 3
// baseline (speedup 1.0000x reference)
#include <cuda_runtime.h>
#include <cstdint>

#define BATCH   2
#define SEQ     2048
#define DMODEL  1024
#define NHEADS  16
#define DHEAD   64
#define N3      3072
#define MROWS   (BATCH * SEQ)

// scratch: [part(3)][b(2)][h(16)][s(2048)][dh(64)]
__device__ float g_qkv[3u * BATCH * NHEADS * SEQ * DHEAD];

typedef unsigned long long u64;

__device__ __forceinline__ u64 pack2(float x, float y) {
    u64 r; asm("mov.b64 %0, {%1, %2};" : "=l"(r) : "f"(x), "f"(y)); return r;
}
__device__ __forceinline__ float2 unpack2(u64 v) {
    float2 r; asm("mov.b64 {%0, %1}, %2;" : "=f"(r.x), "=f"(r.y) : "l"(v)); return r;
}
__device__ __forceinline__ void fma2(u64& d, u64 a, u64 b) {
    asm("fma.rn.f32x2 %0, %1, %2, %0;" : "+l"(d) : "l"(a), "l"(b));
}
__device__ __forceinline__ void mul2(u64& d, u64 a) {
    asm("mul.rn.f32x2 %0, %0, %1;" : "+l"(d) : "l"(a));
}

// ---------------------------------------------------------------------------
// QKV GEMM: C[4096,3072] = x @ W + b, scattered into g_qkv.
// Double-buffered smem, one sync per K-tile.
// ---------------------------------------------------------------------------
__global__ __launch_bounds__(256) void qkv_gemm(const float* __restrict__ x,
                                                const float* __restrict__ W,
                                                const float* __restrict__ bias) {
    __shared__ float As[2][16][128];
    __shared__ float Bs[2][16][128];

    const int t  = threadIdx.x;
    const int tx = t & 15, ty = t >> 4;
    const int n0 = blockIdx.x * 128;
    const int m0 = blockIdx.y * 128;

    const int alr = t >> 2,  alc = (t & 3) << 2;
    const int brw = t >> 5,  bcl = (t & 31) << 2;

    const float* xA0 = &x[(size_t)(m0 + alr)      * DMODEL + alc];
    const float* xA1 = &x[(size_t)(m0 + alr + 64) * DMODEL + alc];
    const float* wB0 = &W[(size_t)(brw)     * N3 + n0 + bcl];
    const float* wB1 = &W[(size_t)(brw + 8) * N3 + n0 + bcl];

    u64 acc[8][4] = {};
    float4 a0, a1, b0, b1;

    // prologue: tile 0 -> buf 0
    a0 = *(const float4*)(xA0);                b0 = *(const float4*)(wB0);
    a1 = *(const float4*)(xA1);                b1 = *(const float4*)(wB1);
    As[0][alc + 0][alr] = a0.x; As[0][alc + 1][alr] = a0.y;
    As[0][alc + 2][alr] = a0.z; As[0][alc + 3][alr] = a0.w;
    As[0][alc + 0][alr + 64] = a1.x; As[0][alc + 1][alr + 64] = a1.y;
    As[0][alc + 2][alr + 64] = a1.z; As[0][alc + 3][alr + 64] = a1.w;
    *(float4*)&Bs[0][brw][bcl]     = b0;
    *(float4*)&Bs[0][brw + 8][bcl] = b1;
    __syncthreads();
    // load tile 1 into regs
    a0 = *(const float4*)(xA0 + 16);           b0 = *(const float4*)(wB0 + 16 * N3);
    a1 = *(const float4*)(xA1 + 16);           b1 = *(const float4*)(wB1 + 16 * N3);

    const int NT = DMODEL / 16;  // 64
    for (int ti = 0; ti < NT; ti++) {
        const int cur = ti & 1, nxt = cur ^ 1;
        if (ti + 1 < NT) {
            As[nxt][alc + 0][alr] = a0.x; As[nxt][alc + 1][alr] = a0.y;
            As[nxt][alc + 2][alr] = a0.z; As[nxt][alc + 3][alr] = a0.w;
            As[nxt][alc + 0][alr + 64] = a1.x; As[nxt][alc + 1][alr + 64] = a1.y;
            As[nxt][alc + 2][alr + 64] = a1.z; As[nxt][alc + 3][alr + 64] = a1.w;
            *(float4*)&Bs[nxt][brw][bcl]     = b0;
            *(float4*)&Bs[nxt][brw + 8][bcl] = b1;
        }
#pragma unroll
        for (int k = 0; k < 16; k++) {
            float4 af0 = *(const float4*)&As[cur][k][ty * 8];
            float4 af1 = *(const float4*)&As[cur][k][ty * 8 + 4];
            ulonglong2 bv0 = *(const ulonglong2*)&Bs[cur][k][tx * 8];
            ulonglong2 bv1 = *(const ulonglong2*)&Bs[cur][k][tx * 8 + 4];
            float a[8] = {af0.x, af0.y, af0.z, af0.w, af1.x, af1.y, af1.z, af1.w};
#pragma unroll
            for (int i = 0; i < 8; i++) {
                u64 a2 = pack2(a[i], a[i]);
                fma2(acc[i][0], a2, bv0.x);
                fma2(acc[i][1], a2, bv0.y);
                fma2(acc[i][2], a2, bv1.x);
                fma2(acc[i][3], a2, bv1.y);
            }
        }
        __syncthreads();
        if (ti + 2 < NT) {
            const int koff = (ti + 2) * 16;
            a0 = *(const float4*)(xA0 + koff);   b0 = *(const float4*)(wB0 + (size_t)koff * N3);
            a1 = *(const float4*)(xA1 + koff);   b1 = *(const float4*)(wB1 + (size_t)koff * N3);
        }
    }

    const int col0 = n0 + tx * 8;
    const int part = col0 >> 10;
    const int h    = (col0 >> 6) & 15;
    const int dh0  = col0 & 63;
    float bs[8];
#pragma unroll
    for (int j = 0; j < 8; j++) bs[j] = bias[col0 + j];

#pragma unroll
    for (int i = 0; i < 8; i++) {
        int row = m0 + ty * 8 + i;
        int bb = row >> 11, s = row & 2047;
        float* dst = g_qkv + ((size_t)((part * 2 + bb) * NHEADS + h) * SEQ + s) * DHEAD + dh0;
        float2 u0 = unpack2(acc[i][0]), u1 = unpack2(acc[i][1]);
        float2 u2 = unpack2(acc[i][2]), u3 = unpack2(acc[i][3]);
        *(float4*)&dst[0] = make_float4(u0.x + bs[0], u0.y + bs[1], u1.x + bs[2], u1.y + bs[3]);
        *(float4*)&dst[4] = make_float4(u2.x + bs[4], u2.y + bs[5], u3.x + bs[6], u3.y + bs[7]);
    }
}

// ---------------------------------------------------------------------------
// Flash attention: 128-query tile, 128 threads (8 tx x 16 ty), 8x8 micro.
// QsT[d][q] and PsT[kk][q] transposed so all smem reads are LDS.128.
// Dynamic smem: QsT 32KB | KV 16KB | PsT 32KB = 80KB.
// ---------------------------------------------------------------------------
__global__ __launch_bounds__(128) void attn_kernel(float* __restrict__ out) {
    extern __shared__ float sm[];
    float* QsT = sm;            // [64][128]
    float* KV  = sm + 8192;     // [64][64]  (K^T then V)
    float* PsT = sm + 12288;    // [64][128]

    const int t  = threadIdx.x;
    const int tx = t & 7, ty = t >> 3;
    const int q0 = blockIdx.x * 128;
    const int h  = blockIdx.y;
    const int bb = blockIdx.z;

    const float* Qg = g_qkv + (size_t)((0 * 2 + bb) * NHEADS + h) * (SEQ * DHEAD);
    const float* Kg = g_qkv + (size_t)((1 * 2 + bb) * NHEADS + h) * (SEQ * DHEAD);
    const float* Vg = g_qkv + (size_t)((2 * 2 + bb) * NHEADS + h) * (SEQ * DHEAD);

    // Load Q transposed: thread t owns global row q0+t.
    {
        const float* src = Qg + (size_t)(q0 + t) * 64;
#pragma unroll
        for (int dc = 0; dc < 16; dc++) {
            float4 v = *(const float4*)&src[dc * 4];
            QsT[(dc * 4 + 0) * 128 + t] = v.x;
            QsT[(dc * 4 + 1) * 128 + t] = v.y;
            QsT[(dc * 4 + 2) * 128 + t] = v.z;
            QsT[(dc * 4 + 3) * 128 + t] = v.w;
        }
    }

    u64 o2[8][4] = {};
    float m_i[8], l_i[8];
#pragma unroll
    for (int i = 0; i < 8; i++) { m_i[i] = -1e30f; l_i[i] = 0.f; }

    for (int kt = 0; kt < SEQ / 64; kt++) {
        const int k0 = kt * 64;
        __syncthreads();  // prior PV done with KV/PsT (and Q store visible, iter 0)

        // K tile transposed: thread owns key k = t&63, d-half (t>>6)*32
        {
            int k = t & 63, d0 = (t >> 6) * 32;
            const float* src = Kg + (size_t)(k0 + k) * 64 + d0;
#pragma unroll
            for (int dc = 0; dc < 8; dc++) {
                float4 v = *(const float4*)&src[dc * 4];
                KV[(d0 + dc * 4 + 0) * 64 + k] = v.x;
                KV[(d0 + dc * 4 + 1) * 64 + k] = v.y;
                KV[(d0 + dc * 4 + 2) * 64 + k] = v.z;
                KV[(d0 + dc * 4 + 3) * 64 + k] = v.w;
            }
        }
        __syncthreads();

        // S = Q @ K^T : 8 q rows (ty) x 8 k cols (tx) per thread
        u64 s2[8][4] = {};
#pragma unroll 8
        for (int d = 0; d < 64; d++) {
            float4 qa = *(const float4*)&QsT[d * 128 + ty * 8];
            float4 qb = *(const float4*)&QsT[d * 128 + ty * 8 + 4];
            ulonglong2 ka = *(const ulonglong2*)&KV[d * 64 + tx * 8];
            ulonglong2 kb = *(const ulonglong2*)&KV[d * 64 + tx * 8 + 4];
            float qq[8] = {qa.x, qa.y, qa.z, qa.w, qb.x, qb.y, qb.z, qb.w};
#pragma unroll
            for (int i = 0; i < 8; i++) {
                u64 q2 = pack2(qq[i], qq[i]);
                fma2(s2[i][0], q2, ka.x);
                fma2(s2[i][1], q2, ka.y);
                fma2(s2[i][2], q2, kb.x);
                fma2(s2[i][3], q2, kb.y);
            }
        }

        // Online softmax: row q spread over 8 tx lanes (shfl xor 1,2,4)
        float p[8][8];
#pragma unroll
        for (int i = 0; i < 8; i++) {
            float2 u0 = unpack2(s2[i][0]), u1 = unpack2(s2[i][1]);
            float2 u2 = unpack2(s2[i][2]), u3 = unpack2(s2[i][3]);
            p[i][0] = u0.x * 0.125f; p[i][1] = u0.y * 0.125f;
            p[i][2] = u1.x * 0.125f; p[i][3] = u1.y * 0.125f;
            p[i][4] = u2.x * 0.125f; p[i][5] = u2.y * 0.125f;
            p[i][6] = u3.x * 0.125f; p[i][7] = u3.y * 0.125f;
            float mt = p[i][0];
#pragma unroll
            for (int j = 1; j < 8; j++) mt = fmaxf(mt, p[i][j]);
            mt = fmaxf(mt, __shfl_xor_sync(0xffffffffu, mt, 1));
            mt = fmaxf(mt, __shfl_xor_sync(0xffffffffu, mt, 2));
            mt = fmaxf(mt, __shfl_xor_sync(0xffffffffu, mt, 4));
            float mn = fmaxf(m_i[i], mt);
            float sc = __expf(m_i[i] - mn);
            m_i[i] = mn;
            float ls = 0.f;
#pragma unroll
            for (int j = 0; j < 8; j++) { p[i][j] = __expf(p[i][j] - mn); ls += p[i][j]; }
            ls += __shfl_xor_sync(0xffffffffu, ls, 1);
            ls += __shfl_xor_sync(0xffffffffu, ls, 2);
            ls += __shfl_xor_sync(0xffffffffu, ls, 4);
            l_i[i] = l_i[i] * sc + ls;
            u64 sc2 = pack2(sc, sc);
            mul2(o2[i][0], sc2); mul2(o2[i][1], sc2);
            mul2(o2[i][2], sc2); mul2(o2[i][3], sc2);
        }
        __syncthreads();  // all warps done reading KV as K

        // Store P transposed [kk][q]; load V natural [kk][d] into KV
#pragma unroll
        for (int j = 0; j < 8; j++) {
            *(float4*)&PsT[(tx * 8 + j) * 128 + ty * 8] =
                make_float4(p[0][j], p[1][j], p[2][j], p[3][j]);
            *(float4*)&PsT[(tx * 8 + j) * 128 + ty * 8 + 4] =
                make_float4(p[4][j], p[5][j], p[6][j], p[7][j]);
        }
        {
            const float* vsrc = Vg + (size_t)k0 * 64;
#pragma unroll
            for (int i = t; i < 1024; i += 128)
                *(float4*)&KV[i * 4] = *(const float4*)&vsrc[i * 4];
        }
        __syncthreads();

        // O += P @ V
#pragma unroll 8
        for (int kk = 0; kk < 64; kk++) {
            float4 pa = *(const float4*)&PsT[kk * 128 + ty * 8];
            float4 pb = *(const float4*)&PsT[kk * 128 + ty * 8 + 4];
            ulonglong2 va = *(const ulonglong2*)&KV[kk * 64 + tx * 8];
            ulonglong2 vb = *(const ulonglong2*)&KV[kk * 64 + tx * 8 + 4];
            float pp[8] = {pa.x, pa.y, pa.z, pa.w, pb.x, pb.y, pb.z, pb.w};
#pragma unroll
            for (int i = 0; i < 8; i++) {
                u64 p2 = pack2(pp[i], pp[i]);
                fma2(o2[i][0], p2, va.x);
                fma2(o2[i][1], p2, va.y);
                fma2(o2[i][2], p2, vb.x);
                fma2(o2[i][3], p2, vb.y);
            }
        }
    }

    // normalize + write out[b][q][h*64 + 8tx .. +8]
#pragma unroll
    for (int i = 0; i < 8; i++) {
        float inv = 1.0f / l_i[i];
        int q = q0 + ty * 8 + i;
        float* dst = out + ((size_t)bb * SEQ + q) * DMODEL + h * DHEAD + tx * 8;
        float2 u0 = unpack2(o2[i][0]), u1 = unpack2(o2[i][1]);
        float2 u2 = unpack2(o2[i][2]), u3 = unpack2(o2[i][3]);
        *(float4*)&dst[0] = make_float4(u0.x * inv, u0.y * inv, u1.x * inv, u1.y * inv);
        *(float4*)&dst[4] = make_float4(u2.x * inv, u2.y * inv, u3.x * inv, u3.y * inv);
    }
}

extern "C" void kernel_launch(void* const* d_in, const int* in_sizes, int n_in,
                              void* d_out, int out_size) {
    const float* x    = (const float*)d_in[0];
    const float* W    = (const float*)d_in[1];
    const float* bias = (const float*)d_in[2];
    float* out = (float*)d_out;

    dim3 ggrid(N3 / 128, MROWS / 128);
    qkv_gemm<<<ggrid, 256>>>(x, W, bias);

    // 80KB dynamic smem (idempotent; not a stream op, capture-safe)
    (void)cudaFuncSetAttribute(attn_kernel,
                               cudaFuncAttributeMaxDynamicSharedMemorySize, 81920);
    dim3 agrid(SEQ / 128, NHEADS, BATCH);
    attn_kernel<<<agrid, 128, 81920>>>(out);
}

// round 4
// speedup vs baseline: 1.1188x; 1.1188x over previous
#include <cuda_runtime.h>
#include <cstdint>

#define BATCH   2
#define SEQ     2048
#define DMODEL  1024
#define NHEADS  16
#define DHEAD   64
#define N3      3072
#define MROWS   (BATCH * SEQ)

// scratch: [part(3)][b(2)][h(16)][s(2048)][dh(64)]
__device__ float g_qkv[3u * BATCH * NHEADS * SEQ * DHEAD];

typedef unsigned long long u64;

__device__ __forceinline__ u64 pack2(float x, float y) {
    u64 r; asm("mov.b64 %0, {%1, %2};" : "=l"(r) : "f"(x), "f"(y)); return r;
}
__device__ __forceinline__ float2 unpack2(u64 v) {
    float2 r; asm("mov.b64 {%0, %1}, %2;" : "=f"(r.x), "=f"(r.y) : "l"(v)); return r;
}
__device__ __forceinline__ void fma2(u64& d, u64 a, u64 b) {
    asm("fma.rn.f32x2 %0, %1, %2, %0;" : "+l"(d) : "l"(a), "l"(b));
}
__device__ __forceinline__ void mul2(u64& d, u64 a) {
    asm("mul.rn.f32x2 %0, %0, %1;" : "+l"(d) : "l"(a));
}

// ---------------------------------------------------------------------------
// QKV GEMM: C[4096,3072] = x @ W + b, scattered into g_qkv.
// Double-buffered smem, one sync per K-tile. (unchanged from R3)
// ---------------------------------------------------------------------------
__global__ __launch_bounds__(256) void qkv_gemm(const float* __restrict__ x,
                                                const float* __restrict__ W,
                                                const float* __restrict__ bias) {
    __shared__ float As[2][16][128];
    __shared__ float Bs[2][16][128];

    const int t  = threadIdx.x;
    const int tx = t & 15, ty = t >> 4;
    const int n0 = blockIdx.x * 128;
    const int m0 = blockIdx.y * 128;

    const int alr = t >> 2,  alc = (t & 3) << 2;
    const int brw = t >> 5,  bcl = (t & 31) << 2;

    const float* xA0 = &x[(size_t)(m0 + alr)      * DMODEL + alc];
    const float* xA1 = &x[(size_t)(m0 + alr + 64) * DMODEL + alc];
    const float* wB0 = &W[(size_t)(brw)     * N3 + n0 + bcl];
    const float* wB1 = &W[(size_t)(brw + 8) * N3 + n0 + bcl];

    u64 acc[8][4] = {};
    float4 a0, a1, b0, b1;

    a0 = *(const float4*)(xA0);                b0 = *(const float4*)(wB0);
    a1 = *(const float4*)(xA1);                b1 = *(const float4*)(wB1);
    As[0][alc + 0][alr] = a0.x; As[0][alc + 1][alr] = a0.y;
    As[0][alc + 2][alr] = a0.z; As[0][alc + 3][alr] = a0.w;
    As[0][alc + 0][alr + 64] = a1.x; As[0][alc + 1][alr + 64] = a1.y;
    As[0][alc + 2][alr + 64] = a1.z; As[0][alc + 3][alr + 64] = a1.w;
    *(float4*)&Bs[0][brw][bcl]     = b0;
    *(float4*)&Bs[0][brw + 8][bcl] = b1;
    __syncthreads();
    a0 = *(const float4*)(xA0 + 16);           b0 = *(const float4*)(wB0 + 16 * N3);
    a1 = *(const float4*)(xA1 + 16);           b1 = *(const float4*)(wB1 + 16 * N3);

    const int NT = DMODEL / 16;
    for (int ti = 0; ti < NT; ti++) {
        const int cur = ti & 1, nxt = cur ^ 1;
        if (ti + 1 < NT) {
            As[nxt][alc + 0][alr] = a0.x; As[nxt][alc + 1][alr] = a0.y;
            As[nxt][alc + 2][alr] = a0.z; As[nxt][alc + 3][alr] = a0.w;
            As[nxt][alc + 0][alr + 64] = a1.x; As[nxt][alc + 1][alr + 64] = a1.y;
            As[nxt][alc + 2][alr + 64] = a1.z; As[nxt][alc + 3][alr + 64] = a1.w;
            *(float4*)&Bs[nxt][brw][bcl]     = b0;
            *(float4*)&Bs[nxt][brw + 8][bcl] = b1;
        }
#pragma unroll
        for (int k = 0; k < 16; k++) {
            float4 af0 = *(const float4*)&As[cur][k][ty * 8];
            float4 af1 = *(const float4*)&As[cur][k][ty * 8 + 4];
            ulonglong2 bv0 = *(const ulonglong2*)&Bs[cur][k][tx * 8];
            ulonglong2 bv1 = *(const ulonglong2*)&Bs[cur][k][tx * 8 + 4];
            float a[8] = {af0.x, af0.y, af0.z, af0.w, af1.x, af1.y, af1.z, af1.w};
#pragma unroll
            for (int i = 0; i < 8; i++) {
                u64 a2 = pack2(a[i], a[i]);
                fma2(acc[i][0], a2, bv0.x);
                fma2(acc[i][1], a2, bv0.y);
                fma2(acc[i][2], a2, bv1.x);
                fma2(acc[i][3], a2, bv1.y);
            }
        }
        __syncthreads();
        if (ti + 2 < NT) {
            const int koff = (ti + 2) * 16;
            a0 = *(const float4*)(xA0 + koff);   b0 = *(const float4*)(wB0 + (size_t)koff * N3);
            a1 = *(const float4*)(xA1 + koff);   b1 = *(const float4*)(wB1 + (size_t)koff * N3);
        }
    }

    const int col0 = n0 + tx * 8;
    const int part = col0 >> 10;
    const int h    = (col0 >> 6) & 15;
    const int dh0  = col0 & 63;
    float bs[8];
#pragma unroll
    for (int j = 0; j < 8; j++) bs[j] = bias[col0 + j];

#pragma unroll
    for (int i = 0; i < 8; i++) {
        int row = m0 + ty * 8 + i;
        int bb = row >> 11, s = row & 2047;
        float* dst = g_qkv + ((size_t)((part * 2 + bb) * NHEADS + h) * SEQ + s) * DHEAD + dh0;
        float2 u0 = unpack2(acc[i][0]), u1 = unpack2(acc[i][1]);
        float2 u2 = unpack2(acc[i][2]), u3 = unpack2(acc[i][3]);
        *(float4*)&dst[0] = make_float4(u0.x + bs[0], u0.y + bs[1], u1.x + bs[2], u1.y + bs[3]);
        *(float4*)&dst[4] = make_float4(u2.x + bs[4], u2.y + bs[5], u3.x + bs[6], u3.y + bs[7]);
    }
}

// ---------------------------------------------------------------------------
// Flash attention v3: 128-query tile, 256 threads (16 tx x 16 ty), 8q x 4k
// micro-tile. QsT[d][q], PsT[kk][q] (pitch 132). 2 CTAs/SM via launch bounds.
// ---------------------------------------------------------------------------
#define P_PITCH 132

__global__ __launch_bounds__(256, 2) void attn_kernel(float* __restrict__ out) {
    extern __shared__ float sm[];
    float* QsT = sm;            // [64][128]  32 KB
    float* KV  = sm + 8192;     // [64][64]   16 KB (K^T then V)
    float* PsT = sm + 12288;    // [64][132]  33 KB

    const int t  = threadIdx.x;
    const int tx = t & 15, ty = t >> 4;
    const int q0 = blockIdx.x * 128;
    const int h  = blockIdx.y;
    const int bb = blockIdx.z;

    const float* Qg = g_qkv + (size_t)((0 * 2 + bb) * NHEADS + h) * (SEQ * DHEAD);
    const float* Kg = g_qkv + (size_t)((1 * 2 + bb) * NHEADS + h) * (SEQ * DHEAD);
    const float* Vg = g_qkv + (size_t)((2 * 2 + bb) * NHEADS + h) * (SEQ * DHEAD);

    // Q transposed: thread owns row q = t&127, d-half (t>>7)*32
    {
        int q = t & 127, d0 = (t >> 7) * 32;
        const float* src = Qg + (size_t)(q0 + q) * 64 + d0;
#pragma unroll
        for (int dc = 0; dc < 8; dc++) {
            float4 v = *(const float4*)&src[dc * 4];
            QsT[(d0 + dc * 4 + 0) * 128 + q] = v.x;
            QsT[(d0 + dc * 4 + 1) * 128 + q] = v.y;
            QsT[(d0 + dc * 4 + 2) * 128 + q] = v.z;
            QsT[(d0 + dc * 4 + 3) * 128 + q] = v.w;
        }
    }

    u64 o2[8][2] = {};
    float m_i[8], l_i[8];
#pragma unroll
    for (int i = 0; i < 8; i++) { m_i[i] = -1e30f; l_i[i] = 0.f; }

    for (int kt = 0; kt < SEQ / 64; kt++) {
        const int k0 = kt * 64;
        __syncthreads();   // prior PV done with KV/PsT; covers Q store at kt=0

        // K^T: thread owns key k = t&63, d-range (t>>6)*16
        {
            int k = t & 63, d0 = (t >> 6) * 16;
            const float* src = Kg + (size_t)(k0 + k) * 64 + d0;
#pragma unroll
            for (int dc = 0; dc < 4; dc++) {
                float4 v = *(const float4*)&src[dc * 4];
                KV[(d0 + dc * 4 + 0) * 64 + k] = v.x;
                KV[(d0 + dc * 4 + 1) * 64 + k] = v.y;
                KV[(d0 + dc * 4 + 2) * 64 + k] = v.z;
                KV[(d0 + dc * 4 + 3) * 64 + k] = v.w;
            }
        }
        __syncthreads();

        // S = Q @ K^T : 8 q (ty*8..) x 4 k (tx*4..)
        u64 s2[8][2] = {};
#pragma unroll 8
        for (int d = 0; d < 64; d++) {
            float4 qa = *(const float4*)&QsT[d * 128 + ty * 8];
            float4 qb = *(const float4*)&QsT[d * 128 + ty * 8 + 4];
            ulonglong2 ka = *(const ulonglong2*)&KV[d * 64 + tx * 4];
            float qq[8] = {qa.x, qa.y, qa.z, qa.w, qb.x, qb.y, qb.z, qb.w};
#pragma unroll
            for (int i = 0; i < 8; i++) {
                u64 q2 = pack2(qq[i], qq[i]);
                fma2(s2[i][0], q2, ka.x);
                fma2(s2[i][1], q2, ka.y);
            }
        }

        // online softmax: each q row spread over 16 tx lanes
        float p[8][4];
#pragma unroll
        for (int i = 0; i < 8; i++) {
            float2 u0 = unpack2(s2[i][0]), u1 = unpack2(s2[i][1]);
            p[i][0] = u0.x * 0.125f; p[i][1] = u0.y * 0.125f;
            p[i][2] = u1.x * 0.125f; p[i][3] = u1.y * 0.125f;
            float mt = fmaxf(fmaxf(p[i][0], p[i][1]), fmaxf(p[i][2], p[i][3]));
            mt = fmaxf(mt, __shfl_xor_sync(0xffffffffu, mt, 1));
            mt = fmaxf(mt, __shfl_xor_sync(0xffffffffu, mt, 2));
            mt = fmaxf(mt, __shfl_xor_sync(0xffffffffu, mt, 4));
            mt = fmaxf(mt, __shfl_xor_sync(0xffffffffu, mt, 8));
            float mn = fmaxf(m_i[i], mt);
            float sc = __expf(m_i[i] - mn);
            m_i[i] = mn;
            float ls = 0.f;
#pragma unroll
            for (int j = 0; j < 4; j++) { p[i][j] = __expf(p[i][j] - mn); ls += p[i][j]; }
            ls += __shfl_xor_sync(0xffffffffu, ls, 1);
            ls += __shfl_xor_sync(0xffffffffu, ls, 2);
            ls += __shfl_xor_sync(0xffffffffu, ls, 4);
            ls += __shfl_xor_sync(0xffffffffu, ls, 8);
            l_i[i] = l_i[i] * sc + ls;
            u64 sc2 = pack2(sc, sc);
            mul2(o2[i][0], sc2); mul2(o2[i][1], sc2);
        }
        __syncthreads();   // done reading KV as K

        // P transposed [kk][q]; V natural [kk][d] into KV
#pragma unroll
        for (int j = 0; j < 4; j++) {
            *(float4*)&PsT[(tx * 4 + j) * P_PITCH + ty * 8] =
                make_float4(p[0][j], p[1][j], p[2][j], p[3][j]);
            *(float4*)&PsT[(tx * 4 + j) * P_PITCH + ty * 8 + 4] =
                make_float4(p[4][j], p[5][j], p[6][j], p[7][j]);
        }
        {
            const float* vsrc = Vg + (size_t)k0 * 64;
#pragma unroll
            for (int i = t; i < 1024; i += 256)
                *(float4*)&KV[i * 4] = *(const float4*)&vsrc[i * 4];
        }
        __syncthreads();

        // O += P @ V : 8 q x 4 d (tx*4..)
#pragma unroll 8
        for (int kk = 0; kk < 64; kk++) {
            float4 pa = *(const float4*)&PsT[kk * P_PITCH + ty * 8];
            float4 pb = *(const float4*)&PsT[kk * P_PITCH + ty * 8 + 4];
            ulonglong2 va = *(const ulonglong2*)&KV[kk * 64 + tx * 4];
            float pp[8] = {pa.x, pa.y, pa.z, pa.w, pb.x, pb.y, pb.z, pb.w};
#pragma unroll
            for (int i = 0; i < 8; i++) {
                u64 p2 = pack2(pp[i], pp[i]);
                fma2(o2[i][0], p2, va.x);
                fma2(o2[i][1], p2, va.y);
            }
        }
    }

    // normalize + write out[b][q][h*64 + tx*4 .. +4]
#pragma unroll
    for (int i = 0; i < 8; i++) {
        float inv = 1.0f / l_i[i];
        int q = q0 + ty * 8 + i;
        float* dst = out + ((size_t)bb * SEQ + q) * DMODEL + h * DHEAD + tx * 4;
        float2 u0 = unpack2(o2[i][0]), u1 = unpack2(o2[i][1]);
        *(float4*)dst = make_float4(u0.x * inv, u0.y * inv, u1.x * inv, u1.y * inv);
    }
}

extern "C" void kernel_launch(void* const* d_in, const int* in_sizes, int n_in,
                              void* d_out, int out_size) {
    const float* x    = (const float*)d_in[0];
    const float* W    = (const float*)d_in[1];
    const float* bias = (const float*)d_in[2];
    float* out = (float*)d_out;

    dim3 ggrid(N3 / 128, MROWS / 128);
    qkv_gemm<<<ggrid, 256>>>(x, W, bias);

    const int smem_bytes = (8192 + 4096 + 64 * P_PITCH) * 4;  // 82944
    (void)cudaFuncSetAttribute(attn_kernel,
                               cudaFuncAttributeMaxDynamicSharedMemorySize, smem_bytes);
    dim3 agrid(SEQ / 128, NHEADS, BATCH);
    attn_kernel<<<agrid, 256, smem_bytes>>>(out);
}

// round 6
// speedup vs baseline: 1.3818x; 1.2350x over previous
#include <cuda_runtime.h>
#include <cuda_bf16.h>
#include <cstdint>

#define BATCH   2
#define SEQ     2048
#define DMODEL  1024
#define NHEADS  16
#define DHEAD   64
#define N3      3072
#define MROWS   (BATCH * SEQ)

__device__ float g_qkv[3u * BATCH * NHEADS * SEQ * DHEAD];
__device__ __nv_bfloat16 g_xh[(size_t)MROWS * DMODEL];
__device__ __nv_bfloat16 g_xl[(size_t)MROWS * DMODEL];
__device__ __nv_bfloat16 g_wht[(size_t)N3 * DMODEL];
__device__ __nv_bfloat16 g_wlt[(size_t)N3 * DMODEL];

typedef unsigned long long u64;

__device__ __forceinline__ u64 pack2(float x, float y) {
    u64 r; asm("mov.b64 %0, {%1, %2};" : "=l"(r) : "f"(x), "f"(y)); return r;
}
__device__ __forceinline__ float2 unpack2(u64 v) {
    float2 r; asm("mov.b64 {%0, %1}, %2;" : "=f"(r.x), "=f"(r.y) : "l"(v)); return r;
}
__device__ __forceinline__ void fma2(u64& d, u64 a, u64 b) {
    asm("fma.rn.f32x2 %0, %1, %2, %0;" : "+l"(d) : "l"(a), "l"(b));
}
__device__ __forceinline__ void mul2(u64& d, u64 a) {
    asm("mul.rn.f32x2 %0, %0, %1;" : "+l"(d) : "l"(a));
}

__device__ __forceinline__ uint32_t smem_u32(const void* p) {
    uint32_t a;
    asm("{ .reg .u64 t; cvta.to.shared.u64 t, %1; cvt.u32.u64 %0, t; }" : "=r"(a) : "l"(p));
    return a;
}
__device__ __forceinline__ void ldmx4(uint32_t* r, uint32_t addr) {
    asm volatile("ldmatrix.sync.aligned.m8n8.x4.shared.b16 {%0,%1,%2,%3}, [%4];"
        : "=r"(r[0]), "=r"(r[1]), "=r"(r[2]), "=r"(r[3]) : "r"(addr));
}
__device__ __forceinline__ void mma_bf16(float* d, const uint32_t* a,
                                         uint32_t b0, uint32_t b1) {
    asm volatile("mma.sync.aligned.m16n8k16.row.col.f32.bf16.bf16.f32 "
        "{%0,%1,%2,%3}, {%4,%5,%6,%7}, {%8,%9}, {%0,%1,%2,%3};"
        : "+f"(d[0]), "+f"(d[1]), "+f"(d[2]), "+f"(d[3])
        : "r"(a[0]), "r"(a[1]), "r"(a[2]), "r"(a[3]), "r"(b0), "r"(b1));
}

__global__ __launch_bounds__(256) void conv_x(const float* __restrict__ in) {
    int i = blockIdx.x * 256 + threadIdx.x;
    float4 v = ((const float4*)in)[i];
    float f[4] = {v.x, v.y, v.z, v.w};
    __nv_bfloat16 h[4], l[4];
#pragma unroll
    for (int j = 0; j < 4; j++) {
        h[j] = __float2bfloat16_rn(f[j]);
        l[j] = __float2bfloat16_rn(f[j] - __bfloat162float(h[j]));
    }
    ((__nv_bfloat162*)g_xh)[2 * i + 0] = {h[0], h[1]};
    ((__nv_bfloat162*)g_xh)[2 * i + 1] = {h[2], h[3]};
    ((__nv_bfloat162*)g_xl)[2 * i + 0] = {l[0], l[1]};
    ((__nv_bfloat162*)g_xl)[2 * i + 1] = {l[2], l[3]};
}

__global__ __launch_bounds__(256) void conv_wT(const float* __restrict__ W) {
    __shared__ float tl[32][33];
    const int tx = threadIdx.x, ty = threadIdx.y;
    const int n0 = blockIdx.x * 32, k0 = blockIdx.y * 32;
#pragma unroll
    for (int j = 0; j < 4; j++)
        tl[ty + j * 8][tx] = W[(size_t)(k0 + ty + j * 8) * N3 + n0 + tx];
    __syncthreads();
#pragma unroll
    for (int j = 0; j < 4; j++) {
        int n = n0 + ty + j * 8, k = k0 + tx;
        float v = tl[tx][ty + j * 8];
        __nv_bfloat16 h = __float2bfloat16_rn(v);
        __nv_bfloat16 l = __float2bfloat16_rn(v - __bfloat162float(h));
        g_wht[(size_t)n * DMODEL + k] = h;
        g_wlt[(size_t)n * DMODEL + k] = l;
    }
}

#define PITCH 80

__global__ __launch_bounds__(256) void gemm_mma(const float* __restrict__ bias) {
    __shared__ __align__(16) char smem[4 * 128 * PITCH];

    const int t   = threadIdx.x;
    const int wid = t >> 5, lid = t & 31;
    const int n0  = blockIdx.x * 128;
    const int m0  = blockIdx.y * 128;
    const int wm  = wid >> 2;
    const int wn  = wid & 3;

    const uint32_t sb = smem_u32(smem);
    const uint32_t sAXH = sb;
    const uint32_t sAXL = sb + 128 * PITCH;
    const uint32_t sBWH = sb + 2 * 128 * PITCH;
    const uint32_t sBWL = sb + 3 * 128 * PITCH;

    const int sub = lid >> 3, r8 = lid & 7;
    const uint32_t lane_off =
        (uint32_t)((r8 + ((sub & 1) << 3)) * PITCH + ((sub >> 1) << 4));

    const __nv_bfloat16* gp[8];
    uint32_t sp[8];
#pragma unroll
    for (int it = 0; it < 8; it++) {
        int idx = t + it * 256;
        int mat = idx >> 9, w = idx & 511;
        int row = w >> 2, c16 = w & 3;
        const __nv_bfloat16* base;
        int grow;
        if (mat == 0)      { base = g_xh;  grow = m0 + row; }
        else if (mat == 1) { base = g_xl;  grow = m0 + row; }
        else if (mat == 2) { base = g_wht; grow = n0 + row; }
        else               { base = g_wlt; grow = n0 + row; }
        gp[it] = base + (size_t)grow * DMODEL + c16 * 8;
        sp[it] = sb + (uint32_t)(mat * 128 * PITCH + row * PITCH + c16 * 16);
    }

    float acc[4][4][4] = {};
    uint4 pf[8];
#pragma unroll
    for (int it = 0; it < 8; it++) pf[it] = *(const uint4*)gp[it];

    for (int ch = 0; ch < DMODEL / 32; ch++) {
        __syncthreads();
#pragma unroll
        for (int it = 0; it < 8; it++)
            asm volatile("st.shared.v4.b32 [%0], {%1,%2,%3,%4};" ::
                "r"(sp[it]), "r"(pf[it].x), "r"(pf[it].y), "r"(pf[it].z), "r"(pf[it].w));
        __syncthreads();

        if (ch + 1 < DMODEL / 32) {
            const int ko = (ch + 1) * 32;
#pragma unroll
            for (int it = 0; it < 8; it++) pf[it] = *(const uint4*)(gp[it] + ko);
        }

#pragma unroll
        for (int ks = 0; ks < 2; ks++) {
            const uint32_t kso = ks * 32;
            uint32_t bh[2][4], bl[2][4];
#pragma unroll
            for (int np = 0; np < 2; np++) {
                uint32_t baddr = (uint32_t)((wn * 32 + np * 16) * PITCH) + kso + lane_off;
                ldmx4(bh[np], sBWH + baddr);
                ldmx4(bl[np], sBWL + baddr);
            }
#pragma unroll
            for (int mt = 0; mt < 4; mt++) {
                uint32_t aaddr = (uint32_t)((wm * 64 + mt * 16) * PITCH) + kso + lane_off;
                uint32_t ah[4], al[4];
                ldmx4(ah, sAXH + aaddr);
                ldmx4(al, sAXL + aaddr);
#pragma unroll
                for (int nt = 0; nt < 4; nt++) {
                    const int np = nt >> 1, o = nt & 1;
                    mma_bf16(acc[mt][nt], ah, bh[np][o], bh[np][2 + o]);
                    mma_bf16(acc[mt][nt], ah, bl[np][o], bl[np][2 + o]);
                    mma_bf16(acc[mt][nt], al, bh[np][o], bh[np][2 + o]);
                }
            }
        }
    }

    const int gid = lid >> 2, tg = lid & 3;
#pragma unroll
    for (int nt = 0; nt < 4; nt++) {
        const int col = n0 + wn * 32 + nt * 8 + tg * 2;
        const float2 bv = *(const float2*)&bias[col];
        const int part = col >> 10, h = (col >> 6) & 15, dh0 = col & 63;
#pragma unroll
        for (int mt = 0; mt < 4; mt++) {
            const int row0 = m0 + wm * 64 + mt * 16 + gid;
#pragma unroll
            for (int half = 0; half < 2; half++) {
                const int row = row0 + half * 8;
                const int bb = row >> 11, s = row & 2047;
                float* dst = g_qkv +
                    ((size_t)((part * 2 + bb) * NHEADS + h) * SEQ + s) * DHEAD + dh0;
                float2 v;
                v.x = acc[mt][nt][2 * half + 0] + bv.x;
                v.y = acc[mt][nt][2 * half + 1] + bv.y;
                *(float2*)dst = v;
            }
        }
    }
}

#define P_PITCH 132

__global__ __launch_bounds__(256, 2) void attn_kernel(float* __restrict__ out) {
    extern __shared__ float sm[];
    float* QsT = sm;
    float* KV  = sm + 8192;
    float* PsT = sm + 12288;

    const int t  = threadIdx.x;
    const int tx = t & 15, ty = t >> 4;
    const int q0 = blockIdx.x * 128;
    const int h  = blockIdx.y;
    const int bb = blockIdx.z;

    const float* Qg = g_qkv + (size_t)((0 * 2 + bb) * NHEADS + h) * (SEQ * DHEAD);
    const float* Kg = g_qkv + (size_t)((1 * 2 + bb) * NHEADS + h) * (SEQ * DHEAD);
    const float* Vg = g_qkv + (size_t)((2 * 2 + bb) * NHEADS + h) * (SEQ * DHEAD);

    {
        int q = t & 127, d0 = (t >> 7) * 32;
        const float* src = Qg + (size_t)(q0 + q) * 64 + d0;
#pragma unroll
        for (int dc = 0; dc < 8; dc++) {
            float4 v = *(const float4*)&src[dc * 4];
            QsT[(d0 + dc * 4 + 0) * 128 + q] = v.x;
            QsT[(d0 + dc * 4 + 1) * 128 + q] = v.y;
            QsT[(d0 + dc * 4 + 2) * 128 + q] = v.z;
            QsT[(d0 + dc * 4 + 3) * 128 + q] = v.w;
        }
    }

    u64 o2[8][2] = {};
    float m_i[8], l_i[8];
#pragma unroll
    for (int i = 0; i < 8; i++) { m_i[i] = -1e30f; l_i[i] = 0.f; }

    for (int kt = 0; kt < SEQ / 64; kt++) {
        const int k0 = kt * 64;
        __syncthreads();

        {
            int k = t & 63, d0 = (t >> 6) * 16;
            const float* src = Kg + (size_t)(k0 + k) * 64 + d0;
#pragma unroll
            for (int dc = 0; dc < 4; dc++) {
                float4 v = *(const float4*)&src[dc * 4];
                KV[(d0 + dc * 4 + 0) * 64 + k] = v.x;
                KV[(d0 + dc * 4 + 1) * 64 + k] = v.y;
                KV[(d0 + dc * 4 + 2) * 64 + k] = v.z;
                KV[(d0 + dc * 4 + 3) * 64 + k] = v.w;
            }
        }
        __syncthreads();

        u64 s2[8][2] = {};
#pragma unroll 8
        for (int d = 0; d < 64; d++) {
            float4 qa = *(const float4*)&QsT[d * 128 + ty * 8];
            float4 qb = *(const float4*)&QsT[d * 128 + ty * 8 + 4];
            ulonglong2 ka = *(const ulonglong2*)&KV[d * 64 + tx * 4];
            float qq[8] = {qa.x, qa.y, qa.z, qa.w, qb.x, qb.y, qb.z, qb.w};
#pragma unroll
            for (int i = 0; i < 8; i++) {
                u64 q2 = pack2(qq[i], qq[i]);
                fma2(s2[i][0], q2, ka.x);
                fma2(s2[i][1], q2, ka.y);
            }
        }

        float p[8][4];
#pragma unroll
        for (int i = 0; i < 8; i++) {
            float2 u0 = unpack2(s2[i][0]), u1 = unpack2(s2[i][1]);
            p[i][0] = u0.x * 0.125f; p[i][1] = u0.y * 0.125f;
            p[i][2] = u1.x * 0.125f; p[i][3] = u1.y * 0.125f;
            float mt = fmaxf(fmaxf(p[i][0], p[i][1]), fmaxf(p[i][2], p[i][3]));
            mt = fmaxf(mt, __shfl_xor_sync(0xffffffffu, mt, 1));
            mt = fmaxf(mt, __shfl_xor_sync(0xffffffffu, mt, 2));
            mt = fmaxf(mt, __shfl_xor_sync(0xffffffffu, mt, 4));
            mt = fmaxf(mt, __shfl_xor_sync(0xffffffffu, mt, 8));
            float mn = fmaxf(m_i[i], mt);
            float sc = __expf(m_i[i] - mn);
            m_i[i] = mn;
            float ls = 0.f;
#pragma unroll
            for (int j = 0; j < 4; j++) { p[i][j] = __expf(p[i][j] - mn); ls += p[i][j]; }
            ls += __shfl_xor_sync(0xffffffffu, ls, 1);
            ls += __shfl_xor_sync(0xffffffffu, ls, 2);
            ls += __shfl_xor_sync(0xffffffffu, ls, 4);
            ls += __shfl_xor_sync(0xffffffffu, ls, 8);
            l_i[i] = l_i[i] * sc + ls;
            u64 sc2 = pack2(sc, sc);
            mul2(o2[i][0], sc2); mul2(o2[i][1], sc2);
        }
        __syncthreads();

#pragma unroll
        for (int j = 0; j < 4; j++) {
            *(float4*)&PsT[(tx * 4 + j) * P_PITCH + ty * 8] =
                make_float4(p[0][j], p[1][j], p[2][j], p[3][j]);
            *(float4*)&PsT[(tx * 4 + j) * P_PITCH + ty * 8 + 4] =
                make_float4(p[4][j], p[5][j], p[6][j], p[7][j]);
        }
        {
            const float* vsrc = Vg + (size_t)k0 * 64;
#pragma unroll
            for (int i = t; i < 1024; i += 256)
                *(float4*)&KV[i * 4] = *(const float4*)&vsrc[i * 4];
        }
        __syncthreads();

#pragma unroll 8
        for (int kk = 0; kk < 64; kk++) {
            float4 pa = *(const float4*)&PsT[kk * P_PITCH + ty * 8];
            float4 pb = *(const float4*)&PsT[kk * P_PITCH + ty * 8 + 4];
            ulonglong2 va = *(const ulonglong2*)&KV[kk * 64 + tx * 4];
            float pp[8] = {pa.x, pa.y, pa.z, pa.w, pb.x, pb.y, pb.z, pb.w};
#pragma unroll
            for (int i = 0; i < 8; i++) {
                u64 p2 = pack2(pp[i], pp[i]);
                fma2(o2[i][0], p2, va.x);
                fma2(o2[i][1], p2, va.y);
            }
        }
    }

#pragma unroll
    for (int i = 0; i < 8; i++) {
        float inv = 1.0f / l_i[i];
        int q = q0 + ty * 8 + i;
        float* dst = out + ((size_t)bb * SEQ + q) * DMODEL + h * DHEAD + tx * 4;
        float2 u0 = unpack2(o2[i][0]), u1 = unpack2(o2[i][1]);
        *(float4*)dst = make_float4(u0.x * inv, u0.y * inv, u1.x * inv, u1.y * inv);
    }
}

extern "C" void kernel_launch(void* const* d_in, const int* in_sizes, int n_in,
                              void* d_out, int out_size) {
    const float* x    = (const float*)d_in[0];
    const float* W    = (const float*)d_in[1];
    const float* bias = (const float*)d_in[2];
    float* out = (float*)d_out;

    conv_x<<<(MROWS * DMODEL / 4) / 256, 256>>>(x);
    conv_wT<<<dim3(N3 / 32, DMODEL / 32), dim3(32, 8)>>>(W);

    gemm_mma<<<dim3(N3 / 128, MROWS / 128), 256>>>(bias);

    const int attn_smem = (8192 + 4096 + 64 * P_PITCH) * 4;
    (void)cudaFuncSetAttribute(attn_kernel,
                               cudaFuncAttributeMaxDynamicSharedMemorySize, attn_smem);
    dim3 agrid(SEQ / 128, NHEADS, BATCH);
    attn_kernel<<<agrid, 256, attn_smem>>>(out);
}

// round 7
// speedup vs baseline: 2.1873x; 1.5829x over previous
#include <cuda_runtime.h>
#include <cuda_bf16.h>
#include <cstdint>

#define BATCH   2
#define SEQ     2048
#define DMODEL  1024
#define NHEADS  16
#define DHEAD   64
#define N3      3072
#define MROWS   (BATCH * SEQ)

// bf16 split GEMM operands
__device__ __nv_bfloat16 g_xh[(size_t)MROWS * DMODEL];
__device__ __nv_bfloat16 g_xl[(size_t)MROWS * DMODEL];
__device__ __nv_bfloat16 g_wht[(size_t)N3 * DMODEL];
__device__ __nv_bfloat16 g_wlt[(size_t)N3 * DMODEL];
// qkv as bf16 hi/lo, layout [b][h][s][dh]
#define QKV_ELEMS ((size_t)BATCH * NHEADS * SEQ * DHEAD)
__device__ __nv_bfloat16 g_qh[QKV_ELEMS];
__device__ __nv_bfloat16 g_ql[QKV_ELEMS];
__device__ __nv_bfloat16 g_kh[QKV_ELEMS];
__device__ __nv_bfloat16 g_kl[QKV_ELEMS];
__device__ __nv_bfloat16 g_vh[QKV_ELEMS];
__device__ __nv_bfloat16 g_vl[QKV_ELEMS];

typedef unsigned long long u64;

__device__ __forceinline__ uint32_t smem_u32(const void* p) {
    uint32_t a;
    asm("{ .reg .u64 t; cvta.to.shared.u64 t, %1; cvt.u32.u64 %0, t; }" : "=r"(a) : "l"(p));
    return a;
}
__device__ __forceinline__ void ldmx4(uint32_t* r, uint32_t addr) {
    asm volatile("ldmatrix.sync.aligned.m8n8.x4.shared.b16 {%0,%1,%2,%3}, [%4];"
        : "=r"(r[0]), "=r"(r[1]), "=r"(r[2]), "=r"(r[3]) : "r"(addr));
}
__device__ __forceinline__ void mma_bf16(float* d, const uint32_t* a,
                                         uint32_t b0, uint32_t b1) {
    asm volatile("mma.sync.aligned.m16n8k16.row.col.f32.bf16.bf16.f32 "
        "{%0,%1,%2,%3}, {%4,%5,%6,%7}, {%8,%9}, {%0,%1,%2,%3};"
        : "+f"(d[0]), "+f"(d[1]), "+f"(d[2]), "+f"(d[3])
        : "r"(a[0]), "r"(a[1]), "r"(a[2]), "r"(a[3]), "r"(b0), "r"(b1));
}
// pack {lo, hi} floats -> bf16x2 (lo in low half)
__device__ __forceinline__ uint32_t cvt2bf(float lo, float hi) {
    uint32_t r;
    asm("cvt.rn.bf16x2.f32 %0, %1, %2;" : "=r"(r) : "f"(hi), "f"(lo));
    return r;
}
__device__ __forceinline__ float ex2(float x) {
    float r; asm("ex2.approx.ftz.f32 %0, %1;" : "=f"(r) : "f"(x)); return r;
}

// ---------------------------------------------------------------------------
// x -> bf16 hi/lo
// ---------------------------------------------------------------------------
__global__ __launch_bounds__(256) void conv_x(const float* __restrict__ in) {
    int i = blockIdx.x * 256 + threadIdx.x;
    float4 v = ((const float4*)in)[i];
    float f[4] = {v.x, v.y, v.z, v.w};
    __nv_bfloat16 h[4], l[4];
#pragma unroll
    for (int j = 0; j < 4; j++) {
        h[j] = __float2bfloat16_rn(f[j]);
        l[j] = __float2bfloat16_rn(f[j] - __bfloat162float(h[j]));
    }
    ((__nv_bfloat162*)g_xh)[2 * i + 0] = {h[0], h[1]};
    ((__nv_bfloat162*)g_xh)[2 * i + 1] = {h[2], h[3]};
    ((__nv_bfloat162*)g_xl)[2 * i + 0] = {l[0], l[1]};
    ((__nv_bfloat162*)g_xl)[2 * i + 1] = {l[2], l[3]};
}

// ---------------------------------------------------------------------------
// W[k][n] -> W^T hi/lo [n][k]
// ---------------------------------------------------------------------------
__global__ __launch_bounds__(256) void conv_wT(const float* __restrict__ W) {
    __shared__ float tl[32][33];
    const int tx = threadIdx.x, ty = threadIdx.y;
    const int n0 = blockIdx.x * 32, k0 = blockIdx.y * 32;
#pragma unroll
    for (int j = 0; j < 4; j++)
        tl[ty + j * 8][tx] = W[(size_t)(k0 + ty + j * 8) * N3 + n0 + tx];
    __syncthreads();
#pragma unroll
    for (int j = 0; j < 4; j++) {
        int n = n0 + ty + j * 8, k = k0 + tx;
        float v = tl[tx][ty + j * 8];
        __nv_bfloat16 h = __float2bfloat16_rn(v);
        __nv_bfloat16 l = __float2bfloat16_rn(v - __bfloat162float(h));
        g_wht[(size_t)n * DMODEL + k] = h;
        g_wlt[(size_t)n * DMODEL + k] = l;
    }
}

// ---------------------------------------------------------------------------
// mma.sync QKV GEMM; epilogue writes bf16 hi/lo q/k/v in [b][h][s][dh]
// ---------------------------------------------------------------------------
#define PITCH 80

__global__ __launch_bounds__(256) void gemm_mma(const float* __restrict__ bias) {
    __shared__ __align__(16) char smem[4 * 128 * PITCH];

    const int t   = threadIdx.x;
    const int wid = t >> 5, lid = t & 31;
    const int n0  = blockIdx.x * 128;
    const int m0  = blockIdx.y * 128;
    const int wm  = wid >> 2;
    const int wn  = wid & 3;

    const uint32_t sb = smem_u32(smem);
    const uint32_t sAXH = sb;
    const uint32_t sAXL = sb + 128 * PITCH;
    const uint32_t sBWH = sb + 2 * 128 * PITCH;
    const uint32_t sBWL = sb + 3 * 128 * PITCH;

    const int sub = lid >> 3, r8 = lid & 7;
    const uint32_t lane_off =
        (uint32_t)((r8 + ((sub & 1) << 3)) * PITCH + ((sub >> 1) << 4));

    const __nv_bfloat16* gp[8];
    uint32_t sp[8];
#pragma unroll
    for (int it = 0; it < 8; it++) {
        int idx = t + it * 256;
        int mat = idx >> 9, w = idx & 511;
        int row = w >> 2, c16 = w & 3;
        const __nv_bfloat16* base;
        int grow;
        if (mat == 0)      { base = g_xh;  grow = m0 + row; }
        else if (mat == 1) { base = g_xl;  grow = m0 + row; }
        else if (mat == 2) { base = g_wht; grow = n0 + row; }
        else               { base = g_wlt; grow = n0 + row; }
        gp[it] = base + (size_t)grow * DMODEL + c16 * 8;
        sp[it] = sb + (uint32_t)(mat * 128 * PITCH + row * PITCH + c16 * 16);
    }

    float acc[4][4][4] = {};
    uint4 pf[8];
#pragma unroll
    for (int it = 0; it < 8; it++) pf[it] = *(const uint4*)gp[it];

    for (int ch = 0; ch < DMODEL / 32; ch++) {
        __syncthreads();
#pragma unroll
        for (int it = 0; it < 8; it++)
            asm volatile("st.shared.v4.b32 [%0], {%1,%2,%3,%4};" ::
                "r"(sp[it]), "r"(pf[it].x), "r"(pf[it].y), "r"(pf[it].z), "r"(pf[it].w));
        __syncthreads();

        if (ch + 1 < DMODEL / 32) {
            const int ko = (ch + 1) * 32;
#pragma unroll
            for (int it = 0; it < 8; it++) pf[it] = *(const uint4*)(gp[it] + ko);
        }

#pragma unroll
        for (int ks = 0; ks < 2; ks++) {
            const uint32_t kso = ks * 32;
            uint32_t bh[2][4], bl[2][4];
#pragma unroll
            for (int np = 0; np < 2; np++) {
                uint32_t baddr = (uint32_t)((wn * 32 + np * 16) * PITCH) + kso + lane_off;
                ldmx4(bh[np], sBWH + baddr);
                ldmx4(bl[np], sBWL + baddr);
            }
#pragma unroll
            for (int mt = 0; mt < 4; mt++) {
                uint32_t aaddr = (uint32_t)((wm * 64 + mt * 16) * PITCH) + kso + lane_off;
                uint32_t ah[4], al[4];
                ldmx4(ah, sAXH + aaddr);
                ldmx4(al, sAXL + aaddr);
#pragma unroll
                for (int nt = 0; nt < 4; nt++) {
                    const int np = nt >> 1, o = nt & 1;
                    mma_bf16(acc[mt][nt], ah, bh[np][o], bh[np][2 + o]);
                    mma_bf16(acc[mt][nt], ah, bl[np][o], bl[np][2 + o]);
                    mma_bf16(acc[mt][nt], al, bh[np][o], bh[np][2 + o]);
                }
            }
        }
    }

    // epilogue: +bias, split to bf16 hi/lo, write q/k/v [b][h][s][dh]
    const int gid = lid >> 2, tg = lid & 3;
    const int part = n0 >> 10;   // constant per CTA (n0 multiple of 128)
    __nv_bfloat16 *ah_ = (part == 0) ? g_qh : (part == 1) ? g_kh : g_vh;
    __nv_bfloat16 *al_ = (part == 0) ? g_ql : (part == 1) ? g_kl : g_vl;

#pragma unroll
    for (int nt = 0; nt < 4; nt++) {
        const int col = n0 + wn * 32 + nt * 8 + tg * 2;
        const float2 bv = *(const float2*)&bias[col];
        const int h = (col >> 6) & 15, dh0 = col & 63;
#pragma unroll
        for (int mt = 0; mt < 4; mt++) {
            const int row0 = m0 + wm * 64 + mt * 16 + gid;
#pragma unroll
            for (int half = 0; half < 2; half++) {
                const int row = row0 + half * 8;
                const int bb = row >> 11, s = row & 2047;
                const size_t idx =
                    ((size_t)(bb * NHEADS + h) * SEQ + s) * DHEAD + dh0;
                float v0 = acc[mt][nt][2 * half + 0] + bv.x;
                float v1 = acc[mt][nt][2 * half + 1] + bv.y;
                uint32_t hp = cvt2bf(v0, v1);
                float f0 = __uint_as_float(hp << 16);
                float f1 = __uint_as_float(hp & 0xffff0000u);
                uint32_t lp = cvt2bf(v0 - f0, v1 - f1);
                *(uint32_t*)(ah_ + idx) = hp;
                *(uint32_t*)(al_ + idx) = lp;
            }
        }
    }
}

// ---------------------------------------------------------------------------
// Tensor-core flash attention. CTA = 128 q, 8 warps x 16q. KV tiles of 64.
// smem rows pitched 144B (odd multiple of 16 -> conflict-free ldmatrix).
// ---------------------------------------------------------------------------
#define AP 144
#define SQH 0
#define SQL (128 * AP)
#define SKH (2 * 128 * AP)
#define SKL (SKH + 64 * AP)
#define SVH (SKL + 64 * AP)
#define SVL (SVH + 64 * AP)
#define ATTN_SMEM (SVL + 64 * AP)   // 73728 B

__global__ __launch_bounds__(256) void attn_mma(float* __restrict__ out) {
    extern __shared__ char sm[];
    const uint32_t sb = smem_u32(sm);
    const int t = threadIdx.x, w = t >> 5, lid = t & 31;
    const int gid = lid >> 2, tg = lid & 3;
    const int sub = lid >> 3, r8 = lid & 7;
    const uint32_t lane_off =
        (uint32_t)((r8 + ((sub & 1) << 3)) * AP + ((sub >> 1) << 4));

    const int q0 = blockIdx.x * 128;
    const int h  = blockIdx.y;
    const int bb = blockIdx.z;
    const size_t base = (size_t)(bb * NHEADS + h) * SEQ * DHEAD;

    // load Q hi/lo: 1024 16B-slots per array (128 rows x 8)
#pragma unroll
    for (int i = 0; i < 4; i++) {
        int idx = t + i * 256;
        int row = idx >> 3, c16 = idx & 7;
        const size_t g = base + (size_t)(q0 + row) * DHEAD + c16 * 8;
        uint4 vh = *(const uint4*)(g_qh + g);
        uint4 vl = *(const uint4*)(g_ql + g);
        uint32_t d = sb + (uint32_t)(row * AP + c16 * 16);
        asm volatile("st.shared.v4.b32 [%0], {%1,%2,%3,%4};" ::
            "r"(d + SQH), "r"(vh.x), "r"(vh.y), "r"(vh.z), "r"(vh.w));
        asm volatile("st.shared.v4.b32 [%0], {%1,%2,%3,%4};" ::
            "r"(d + SQL), "r"(vl.x), "r"(vl.y), "r"(vl.z), "r"(vl.w));
    }

    float oacc[8][4] = {};
    float m0 = -1e30f, m1 = -1e30f, l0 = 0.f, l1 = 0.f;
    const float SL2E = 0.125f * 1.4426950408889634f;

    for (int kt = 0; kt < SEQ / 64; kt++) {
        const int k0 = kt * 64;
        __syncthreads();   // prev tile consumed; covers Q stores at kt=0

        // K hi/lo: 512 slots each
#pragma unroll
        for (int i = 0; i < 2; i++) {
            int idx = t + i * 256;
            int row = idx >> 3, c16 = idx & 7;
            const size_t g = base + (size_t)(k0 + row) * DHEAD + c16 * 8;
            uint4 vh = *(const uint4*)(g_kh + g);
            uint4 vl = *(const uint4*)(g_kl + g);
            uint32_t d = sb + (uint32_t)(row * AP + c16 * 16);
            asm volatile("st.shared.v4.b32 [%0], {%1,%2,%3,%4};" ::
                "r"(d + SKH), "r"(vh.x), "r"(vh.y), "r"(vh.z), "r"(vh.w));
            asm volatile("st.shared.v4.b32 [%0], {%1,%2,%3,%4};" ::
                "r"(d + SKL), "r"(vl.x), "r"(vl.y), "r"(vl.z), "r"(vl.w));
        }
        // V transposed into [dh][key]: thread owns key pair kp, 8 dh values
        {
            const int kp = t & 31, dhg = t >> 5;
            const size_t g0 = base + (size_t)(k0 + 2 * kp) * DHEAD + dhg * 8;
            uint4 a_h = *(const uint4*)(g_vh + g0);
            uint4 b_h = *(const uint4*)(g_vh + g0 + DHEAD);
            uint4 a_l = *(const uint4*)(g_vl + g0);
            uint4 b_l = *(const uint4*)(g_vl + g0 + DHEAD);
            const ushort* ah = (const ushort*)&a_h;
            const ushort* bh = (const ushort*)&b_h;
            const ushort* al = (const ushort*)&a_l;
            const ushort* bl = (const ushort*)&b_l;
#pragma unroll
            for (int i = 0; i < 8; i++) {
                uint32_t ph = (uint32_t)ah[i] | ((uint32_t)bh[i] << 16);
                uint32_t pl = (uint32_t)al[i] | ((uint32_t)bl[i] << 16);
                uint32_t d = sb + (uint32_t)((dhg * 8 + i) * AP + kp * 4);
                asm volatile("st.shared.b32 [%0], %1;" :: "r"(d + SVH), "r"(ph));
                asm volatile("st.shared.b32 [%0], %1;" :: "r"(d + SVL), "r"(pl));
            }
        }
        __syncthreads();

        // ---- S = Q K^T (3-term split) ----
        float sacc[8][4] = {};
#pragma unroll
        for (int kc = 0; kc < 4; kc++) {
            uint32_t qh4[4], ql4[4];
            const uint32_t qa = sb + (uint32_t)(w * 16 * AP) + kc * 32 + lane_off;
            ldmx4(qh4, qa + SQH);
            ldmx4(ql4, qa + SQL);
#pragma unroll
            for (int np = 0; np < 4; np++) {
                uint32_t kh4[4], kl4[4];
                const uint32_t ka = sb + (uint32_t)(np * 16 * AP) + kc * 32 + lane_off;
                ldmx4(kh4, ka + SKH);
                ldmx4(kl4, ka + SKL);
#pragma unroll
                for (int o = 0; o < 2; o++) {
                    const int nt = 2 * np + o;
                    mma_bf16(sacc[nt], qh4, kh4[o], kh4[2 + o]);
                    mma_bf16(sacc[nt], qh4, kl4[o], kl4[2 + o]);
                    mma_bf16(sacc[nt], ql4, kh4[o], kh4[2 + o]);
                }
            }
        }

        // ---- online softmax (raw-max, base-2 exp) ----
        float mx0 = sacc[0][0], mx1 = sacc[0][2];
#pragma unroll
        for (int j = 0; j < 8; j++) {
            mx0 = fmaxf(mx0, fmaxf(sacc[j][0], sacc[j][1]));
            mx1 = fmaxf(mx1, fmaxf(sacc[j][2], sacc[j][3]));
        }
        mx0 = fmaxf(mx0, __shfl_xor_sync(0xffffffffu, mx0, 1));
        mx0 = fmaxf(mx0, __shfl_xor_sync(0xffffffffu, mx0, 2));
        mx1 = fmaxf(mx1, __shfl_xor_sync(0xffffffffu, mx1, 1));
        mx1 = fmaxf(mx1, __shfl_xor_sync(0xffffffffu, mx1, 2));
        const float nm0 = fmaxf(m0, mx0), nm1 = fmaxf(m1, mx1);
        const float sc0 = ex2((m0 - nm0) * SL2E);
        const float sc1 = ex2((m1 - nm1) * SL2E);
        m0 = nm0; m1 = nm1;
        float ls0 = 0.f, ls1 = 0.f;
#pragma unroll
        for (int j = 0; j < 8; j++) {
            sacc[j][0] = ex2((sacc[j][0] - nm0) * SL2E);
            sacc[j][1] = ex2((sacc[j][1] - nm0) * SL2E);
            sacc[j][2] = ex2((sacc[j][2] - nm1) * SL2E);
            sacc[j][3] = ex2((sacc[j][3] - nm1) * SL2E);
            ls0 += sacc[j][0] + sacc[j][1];
            ls1 += sacc[j][2] + sacc[j][3];
        }
        ls0 += __shfl_xor_sync(0xffffffffu, ls0, 1);
        ls0 += __shfl_xor_sync(0xffffffffu, ls0, 2);
        ls1 += __shfl_xor_sync(0xffffffffu, ls1, 1);
        ls1 += __shfl_xor_sync(0xffffffffu, ls1, 2);
        l0 = l0 * sc0 + ls0;
        l1 = l1 * sc1 + ls1;
#pragma unroll
        for (int j = 0; j < 8; j++) {
            oacc[j][0] *= sc0; oacc[j][1] *= sc0;
            oacc[j][2] *= sc1; oacc[j][3] *= sc1;
        }

        // ---- O += P V (P hi/lo from registers, V from transposed smem) ----
#pragma unroll
        for (int kc = 0; kc < 4; kc++) {
            const int j0 = 2 * kc, j1 = 2 * kc + 1;
            uint32_t pah[4], pal[4];
            {
                float e0, e1;
                pah[0] = cvt2bf(sacc[j0][0], sacc[j0][1]);
                e0 = sacc[j0][0] - __uint_as_float(pah[0] << 16);
                e1 = sacc[j0][1] - __uint_as_float(pah[0] & 0xffff0000u);
                pal[0] = cvt2bf(e0, e1);
                pah[1] = cvt2bf(sacc[j0][2], sacc[j0][3]);
                e0 = sacc[j0][2] - __uint_as_float(pah[1] << 16);
                e1 = sacc[j0][3] - __uint_as_float(pah[1] & 0xffff0000u);
                pal[1] = cvt2bf(e0, e1);
                pah[2] = cvt2bf(sacc[j1][0], sacc[j1][1]);
                e0 = sacc[j1][0] - __uint_as_float(pah[2] << 16);
                e1 = sacc[j1][1] - __uint_as_float(pah[2] & 0xffff0000u);
                pal[2] = cvt2bf(e0, e1);
                pah[3] = cvt2bf(sacc[j1][2], sacc[j1][3]);
                e0 = sacc[j1][2] - __uint_as_float(pah[3] << 16);
                e1 = sacc[j1][3] - __uint_as_float(pah[3] & 0xffff0000u);
                pal[3] = cvt2bf(e0, e1);
            }
#pragma unroll
            for (int np = 0; np < 4; np++) {
                uint32_t vh4[4], vl4[4];
                const uint32_t va = sb + (uint32_t)(np * 16 * AP) + kc * 32 + lane_off;
                ldmx4(vh4, va + SVH);
                ldmx4(vl4, va + SVL);
#pragma unroll
                for (int o = 0; o < 2; o++) {
                    const int nt = 2 * np + o;
                    mma_bf16(oacc[nt], pah, vh4[o], vh4[2 + o]);
                    mma_bf16(oacc[nt], pah, vl4[o], vl4[2 + o]);
                    mma_bf16(oacc[nt], pal, vh4[o], vh4[2 + o]);
                }
            }
        }
    }

    // ---- normalize + write out[b][q][h*64+dh] ----
    const float inv0 = 1.0f / l0, inv1 = 1.0f / l1;
    const int qa = q0 + w * 16 + gid;
    const int qb = qa + 8;
#pragma unroll
    for (int j = 0; j < 8; j++) {
        const int col = h * DHEAD + 8 * j + 2 * tg;
        float2 v0 = {oacc[j][0] * inv0, oacc[j][1] * inv0};
        float2 v1 = {oacc[j][2] * inv1, oacc[j][3] * inv1};
        *(float2*)(out + ((size_t)bb * SEQ + qa) * DMODEL + col) = v0;
        *(float2*)(out + ((size_t)bb * SEQ + qb) * DMODEL + col) = v1;
    }
}

extern "C" void kernel_launch(void* const* d_in, const int* in_sizes, int n_in,
                              void* d_out, int out_size) {
    const float* x    = (const float*)d_in[0];
    const float* W    = (const float*)d_in[1];
    const float* bias = (const float*)d_in[2];
    float* out = (float*)d_out;

    conv_x<<<(MROWS * DMODEL / 4) / 256, 256>>>(x);
    conv_wT<<<dim3(N3 / 32, DMODEL / 32), dim3(32, 8)>>>(W);

    gemm_mma<<<dim3(N3 / 128, MROWS / 128), 256>>>(bias);

    (void)cudaFuncSetAttribute(attn_mma,
                               cudaFuncAttributeMaxDynamicSharedMemorySize, ATTN_SMEM);
    dim3 agrid(SEQ / 128, NHEADS, BATCH);
    attn_mma<<<agrid, 256, ATTN_SMEM>>>(out);
}

// round 8
// speedup vs baseline: 2.8214x; 1.2899x over previous
#include <cuda_runtime.h>
#include <cuda_bf16.h>
#include <cstdint>

#define BATCH   2
#define SEQ     2048
#define DMODEL  1024
#define NHEADS  16
#define DHEAD   64
#define N3      3072
#define MROWS   (BATCH * SEQ)

// bf16 split GEMM operands
__device__ __nv_bfloat16 g_xh[(size_t)MROWS * DMODEL];
__device__ __nv_bfloat16 g_xl[(size_t)MROWS * DMODEL];
__device__ __nv_bfloat16 g_wht[(size_t)N3 * DMODEL];
__device__ __nv_bfloat16 g_wlt[(size_t)N3 * DMODEL];
// qkv as bf16 hi/lo, layout [b][h][s][dh]
#define QKV_ELEMS ((size_t)BATCH * NHEADS * SEQ * DHEAD)
__device__ __nv_bfloat16 g_qh[QKV_ELEMS];
__device__ __nv_bfloat16 g_ql[QKV_ELEMS];
__device__ __nv_bfloat16 g_kh[QKV_ELEMS];
__device__ __nv_bfloat16 g_kl[QKV_ELEMS];
__device__ __nv_bfloat16 g_vh[QKV_ELEMS];
__device__ __nv_bfloat16 g_vl[QKV_ELEMS];

typedef unsigned long long u64;

__device__ __forceinline__ uint32_t smem_u32(const void* p) {
    uint32_t a;
    asm("{ .reg .u64 t; cvta.to.shared.u64 t, %1; cvt.u32.u64 %0, t; }" : "=r"(a) : "l"(p));
    return a;
}
__device__ __forceinline__ void ldmx4(uint32_t* r, uint32_t addr) {
    asm volatile("ldmatrix.sync.aligned.m8n8.x4.shared.b16 {%0,%1,%2,%3}, [%4];"
        : "=r"(r[0]), "=r"(r[1]), "=r"(r[2]), "=r"(r[3]) : "r"(addr));
}
__device__ __forceinline__ void ldmx4t(uint32_t* r, uint32_t addr) {
    asm volatile("ldmatrix.sync.aligned.m8n8.x4.trans.shared.b16 {%0,%1,%2,%3}, [%4];"
        : "=r"(r[0]), "=r"(r[1]), "=r"(r[2]), "=r"(r[3]) : "r"(addr));
}
__device__ __forceinline__ void mma_bf16(float* d, const uint32_t* a,
                                         uint32_t b0, uint32_t b1) {
    asm volatile("mma.sync.aligned.m16n8k16.row.col.f32.bf16.bf16.f32 "
        "{%0,%1,%2,%3}, {%4,%5,%6,%7}, {%8,%9}, {%0,%1,%2,%3};"
        : "+f"(d[0]), "+f"(d[1]), "+f"(d[2]), "+f"(d[3])
        : "r"(a[0]), "r"(a[1]), "r"(a[2]), "r"(a[3]), "r"(b0), "r"(b1));
}
__device__ __forceinline__ uint32_t cvt2bf(float lo, float hi) {
    uint32_t r;
    asm("cvt.rn.bf16x2.f32 %0, %1, %2;" : "=r"(r) : "f"(hi), "f"(lo));
    return r;
}
__device__ __forceinline__ float ex2(float x) {
    float r; asm("ex2.approx.ftz.f32 %0, %1;" : "=f"(r) : "f"(x)); return r;
}
__device__ __forceinline__ void cp16(uint32_t d, const void* g) {
    asm volatile("cp.async.cg.shared.global [%0], [%1], 16;" :: "r"(d), "l"(g) : "memory");
}
#define CP_COMMIT() asm volatile("cp.async.commit_group;" ::: "memory")
#define CP_WAIT0()  asm volatile("cp.async.wait_group 0;" ::: "memory")
#define CP_WAIT1()  asm volatile("cp.async.wait_group 1;" ::: "memory")

// ---------------------------------------------------------------------------
// x -> bf16 hi/lo
// ---------------------------------------------------------------------------
__global__ __launch_bounds__(256) void conv_x(const float* __restrict__ in) {
    int i = blockIdx.x * 256 + threadIdx.x;
    float4 v = ((const float4*)in)[i];
    float f[4] = {v.x, v.y, v.z, v.w};
    __nv_bfloat16 h[4], l[4];
#pragma unroll
    for (int j = 0; j < 4; j++) {
        h[j] = __float2bfloat16_rn(f[j]);
        l[j] = __float2bfloat16_rn(f[j] - __bfloat162float(h[j]));
    }
    ((__nv_bfloat162*)g_xh)[2 * i + 0] = {h[0], h[1]};
    ((__nv_bfloat162*)g_xh)[2 * i + 1] = {h[2], h[3]};
    ((__nv_bfloat162*)g_xl)[2 * i + 0] = {l[0], l[1]};
    ((__nv_bfloat162*)g_xl)[2 * i + 1] = {l[2], l[3]};
}

// ---------------------------------------------------------------------------
// W[k][n] -> W^T hi/lo [n][k]
// ---------------------------------------------------------------------------
__global__ __launch_bounds__(256) void conv_wT(const float* __restrict__ W) {
    __shared__ float tl[32][33];
    const int tx = threadIdx.x, ty = threadIdx.y;
    const int n0 = blockIdx.x * 32, k0 = blockIdx.y * 32;
#pragma unroll
    for (int j = 0; j < 4; j++)
        tl[ty + j * 8][tx] = W[(size_t)(k0 + ty + j * 8) * N3 + n0 + tx];
    __syncthreads();
#pragma unroll
    for (int j = 0; j < 4; j++) {
        int n = n0 + ty + j * 8, k = k0 + tx;
        float v = tl[tx][ty + j * 8];
        __nv_bfloat16 h = __float2bfloat16_rn(v);
        __nv_bfloat16 l = __float2bfloat16_rn(v - __bfloat162float(h));
        g_wht[(size_t)n * DMODEL + k] = h;
        g_wlt[(size_t)n * DMODEL + k] = l;
    }
}

// ---------------------------------------------------------------------------
// mma.sync QKV GEMM, cp.async double-buffered.
// ---------------------------------------------------------------------------
#define PITCH 80
#define GB (4 * 128 * PITCH)       // 40960 per buffer
#define GEMM_SMEM (2 * GB)         // 81920

__global__ __launch_bounds__(256, 2) void gemm_mma(const float* __restrict__ bias) {
    extern __shared__ char smem[];

    const int t   = threadIdx.x;
    const int wid = t >> 5, lid = t & 31;
    const int n0  = blockIdx.x * 128;
    const int m0  = blockIdx.y * 128;
    const int wm  = wid >> 2;
    const int wn  = wid & 3;

    const uint32_t sb = smem_u32(smem);
    const int sub = lid >> 3, r8 = lid & 7;
    const uint32_t lane_off =
        (uint32_t)((r8 + ((sub & 1) << 3)) * PITCH + ((sub >> 1) << 4));

    const __nv_bfloat16* gp[8];
    uint32_t sp[8];
#pragma unroll
    for (int it = 0; it < 8; it++) {
        int idx = t + it * 256;
        int mat = idx >> 9, w = idx & 511;
        int row = w >> 2, c16 = w & 3;
        const __nv_bfloat16* base;
        int grow;
        if (mat == 0)      { base = g_xh;  grow = m0 + row; }
        else if (mat == 1) { base = g_xl;  grow = m0 + row; }
        else if (mat == 2) { base = g_wht; grow = n0 + row; }
        else               { base = g_wlt; grow = n0 + row; }
        gp[it] = base + (size_t)grow * DMODEL + c16 * 8;
        sp[it] = sb + (uint32_t)(mat * 128 * PITCH + row * PITCH + c16 * 16);
    }

    // prologue: chunks 0,1 in flight
#pragma unroll
    for (int it = 0; it < 8; it++) cp16(sp[it], gp[it]);
    CP_COMMIT();
#pragma unroll
    for (int it = 0; it < 8; it++) cp16(sp[it] + GB, gp[it] + 32);
    CP_COMMIT();

    float acc[4][4][4] = {};

    for (int ch = 0; ch < DMODEL / 32; ch++) {
        if (ch == DMODEL / 32 - 1) { CP_WAIT0(); } else { CP_WAIT1(); }
        __syncthreads();
        const uint32_t bo = (uint32_t)((ch & 1) * GB);
        const uint32_t sAXH = sb + bo;
        const uint32_t sAXL = sAXH + 128 * PITCH;
        const uint32_t sBWH = sAXH + 2 * 128 * PITCH;
        const uint32_t sBWL = sAXH + 3 * 128 * PITCH;

#pragma unroll
        for (int ks = 0; ks < 2; ks++) {
            const uint32_t kso = ks * 32;
            uint32_t bh[2][4], bl[2][4];
#pragma unroll
            for (int np = 0; np < 2; np++) {
                uint32_t baddr = (uint32_t)((wn * 32 + np * 16) * PITCH) + kso + lane_off;
                ldmx4(bh[np], sBWH + baddr);
                ldmx4(bl[np], sBWL + baddr);
            }
#pragma unroll
            for (int mt = 0; mt < 4; mt++) {
                uint32_t aaddr = (uint32_t)((wm * 64 + mt * 16) * PITCH) + kso + lane_off;
                uint32_t ah[4], al[4];
                ldmx4(ah, sAXH + aaddr);
                ldmx4(al, sAXL + aaddr);
#pragma unroll
                for (int nt = 0; nt < 4; nt++) {
                    const int np = nt >> 1, o = nt & 1;
                    mma_bf16(acc[mt][nt], ah, bh[np][o], bh[np][2 + o]);
                    mma_bf16(acc[mt][nt], ah, bl[np][o], bl[np][2 + o]);
                    mma_bf16(acc[mt][nt], al, bh[np][o], bh[np][2 + o]);
                }
            }
        }
        __syncthreads();
        if (ch + 2 < DMODEL / 32) {
            const int ko = (ch + 2) * 32;
#pragma unroll
            for (int it = 0; it < 8; it++) cp16(sp[it] + bo, gp[it] + ko);
            CP_COMMIT();
        }
    }

    // epilogue: +bias, split to bf16 hi/lo, write q/k/v [b][h][s][dh]
    const int gid = lid >> 2, tg = lid & 3;
    const int part = n0 >> 10;
    __nv_bfloat16 *ah_ = (part == 0) ? g_qh : (part == 1) ? g_kh : g_vh;
    __nv_bfloat16 *al_ = (part == 0) ? g_ql : (part == 1) ? g_kl : g_vl;

#pragma unroll
    for (int nt = 0; nt < 4; nt++) {
        const int col = n0 + wn * 32 + nt * 8 + tg * 2;
        const float2 bv = *(const float2*)&bias[col];
        const int h = (col >> 6) & 15, dh0 = col & 63;
#pragma unroll
        for (int mt = 0; mt < 4; mt++) {
            const int row0 = m0 + wm * 64 + mt * 16 + gid;
#pragma unroll
            for (int half = 0; half < 2; half++) {
                const int row = row0 + half * 8;
                const int bb = row >> 11, s = row & 2047;
                const size_t idx =
                    ((size_t)(bb * NHEADS + h) * SEQ + s) * DHEAD + dh0;
                float v0 = acc[mt][nt][2 * half + 0] + bv.x;
                float v1 = acc[mt][nt][2 * half + 1] + bv.y;
                uint32_t hp = cvt2bf(v0, v1);
                float f0 = __uint_as_float(hp << 16);
                float f1 = __uint_as_float(hp & 0xffff0000u);
                uint32_t lp = cvt2bf(v0 - f0, v1 - f1);
                *(uint32_t*)(ah_ + idx) = hp;
                *(uint32_t*)(al_ + idx) = lp;
            }
        }
    }
}

// ---------------------------------------------------------------------------
// Tensor-core flash attention, cp.async double-buffered KV, ldmatrix.trans V.
// smem: Q hi/lo (128 rows) | 2 x [K hi/lo + V hi/lo] (64 rows each), pitch 144.
// ---------------------------------------------------------------------------
#define AP 144
#define SQH 0
#define SQL (128 * AP)             // 18432
#define KVBUF0 (2 * 128 * AP)      // 36864
#define KVSZ (4 * 64 * AP)         // 36864 (KH 0 | KL 9216 | VH 18432 | VL 27648)
#define ATTN_SMEM (KVBUF0 + 2 * KVSZ)   // 110592

__global__ __launch_bounds__(256, 2) void attn_mma(float* __restrict__ out) {
    extern __shared__ char sm[];
    const uint32_t sb = smem_u32(sm);
    const int t = threadIdx.x, w = t >> 5, lid = t & 31;
    const int gid = lid >> 2, tg = lid & 3;
    const int sub = lid >> 3, r8 = lid & 7;
    const uint32_t lane_off =
        (uint32_t)((r8 + ((sub & 1) << 3)) * AP + ((sub >> 1) << 4));

    const int q0 = blockIdx.x * 128;
    const int h  = blockIdx.y;
    const int bb = blockIdx.z;
    const size_t base = (size_t)(bb * NHEADS + h) * SEQ * DHEAD;

    const int row = t >> 3, c16 = t & 7;   // row 0..31, c16 0..7

    // issue KV tile (64 rows: row, row+32) into buffer at smem offset kvb
#define ISSUE_KV(k0_, kvb_) do {                                               \
        size_t g_ = base + (size_t)((k0_) + row) * DHEAD + c16 * 8;            \
        uint32_t d_ = sb + (uint32_t)(kvb_) + (uint32_t)(row * AP + c16 * 16); \
        cp16(d_ + 0,     g_kh + g_);                                           \
        cp16(d_ + 9216,  g_kl + g_);                                           \
        cp16(d_ + 18432, g_vh + g_);                                           \
        cp16(d_ + 27648, g_vl + g_);                                           \
        g_ += 32 * DHEAD; d_ += 32 * AP;                                       \
        cp16(d_ + 0,     g_kh + g_);                                           \
        cp16(d_ + 9216,  g_kl + g_);                                           \
        cp16(d_ + 18432, g_vh + g_);                                           \
        cp16(d_ + 27648, g_vl + g_);                                           \
    } while (0)

    // Q (128 rows) + KV tile 0 -> group 0; KV tile 1 -> group 1
#pragma unroll
    for (int i = 0; i < 4; i++) {
        const int qr = row + 32 * i;
        const size_t g = base + (size_t)(q0 + qr) * DHEAD + c16 * 8;
        const uint32_t d = sb + (uint32_t)(qr * AP + c16 * 16);
        cp16(d + SQH, g_qh + g);
        cp16(d + SQL, g_ql + g);
    }
    ISSUE_KV(0, KVBUF0);
    CP_COMMIT();
    ISSUE_KV(64, KVBUF0 + KVSZ);
    CP_COMMIT();

    float oacc[8][4] = {};
    float m0 = -1e30f, m1 = -1e30f, l0 = 0.f, l1 = 0.f;
    const float SL2E = 0.125f * 1.4426950408889634f;

    for (int kt = 0; kt < SEQ / 64; kt++) {
        if (kt == SEQ / 64 - 1) { CP_WAIT0(); } else { CP_WAIT1(); }
        __syncthreads();
        const uint32_t kvb = sb + (uint32_t)(KVBUF0 + (kt & 1) * KVSZ);

        // ---- S = Q K^T (3-term split) ----
        float sacc[8][4] = {};
#pragma unroll
        for (int kc = 0; kc < 4; kc++) {
            uint32_t qh4[4], ql4[4];
            const uint32_t qa = sb + (uint32_t)(w * 16 * AP) + kc * 32 + lane_off;
            ldmx4(qh4, qa + SQH);
            ldmx4(ql4, qa + SQL);
#pragma unroll
            for (int np = 0; np < 4; np++) {
                uint32_t kh4[4], kl4[4];
                const uint32_t ka = kvb + (uint32_t)(np * 16 * AP) + kc * 32 + lane_off;
                ldmx4(kh4, ka);
                ldmx4(kl4, ka + 9216);
#pragma unroll
                for (int o = 0; o < 2; o++) {
                    const int nt = 2 * np + o;
                    mma_bf16(sacc[nt], qh4, kh4[o], kh4[2 + o]);
                    mma_bf16(sacc[nt], qh4, kl4[o], kl4[2 + o]);
                    mma_bf16(sacc[nt], ql4, kh4[o], kh4[2 + o]);
                }
            }
        }

        // ---- online softmax (base-2 exp) ----
        float mx0 = sacc[0][0], mx1 = sacc[0][2];
#pragma unroll
        for (int j = 0; j < 8; j++) {
            mx0 = fmaxf(mx0, fmaxf(sacc[j][0], sacc[j][1]));
            mx1 = fmaxf(mx1, fmaxf(sacc[j][2], sacc[j][3]));
        }
        mx0 = fmaxf(mx0, __shfl_xor_sync(0xffffffffu, mx0, 1));
        mx0 = fmaxf(mx0, __shfl_xor_sync(0xffffffffu, mx0, 2));
        mx1 = fmaxf(mx1, __shfl_xor_sync(0xffffffffu, mx1, 1));
        mx1 = fmaxf(mx1, __shfl_xor_sync(0xffffffffu, mx1, 2));
        const float nm0 = fmaxf(m0, mx0), nm1 = fmaxf(m1, mx1);
        const float sc0 = ex2((m0 - nm0) * SL2E);
        const float sc1 = ex2((m1 - nm1) * SL2E);
        m0 = nm0; m1 = nm1;
        float ls0 = 0.f, ls1 = 0.f;
#pragma unroll
        for (int j = 0; j < 8; j++) {
            sacc[j][0] = ex2((sacc[j][0] - nm0) * SL2E);
            sacc[j][1] = ex2((sacc[j][1] - nm0) * SL2E);
            sacc[j][2] = ex2((sacc[j][2] - nm1) * SL2E);
            sacc[j][3] = ex2((sacc[j][3] - nm1) * SL2E);
            ls0 += sacc[j][0] + sacc[j][1];
            ls1 += sacc[j][2] + sacc[j][3];
        }
        ls0 += __shfl_xor_sync(0xffffffffu, ls0, 1);
        ls0 += __shfl_xor_sync(0xffffffffu, ls0, 2);
        ls1 += __shfl_xor_sync(0xffffffffu, ls1, 1);
        ls1 += __shfl_xor_sync(0xffffffffu, ls1, 2);
        l0 = l0 * sc0 + ls0;
        l1 = l1 * sc1 + ls1;
#pragma unroll
        for (int j = 0; j < 8; j++) {
            oacc[j][0] *= sc0; oacc[j][1] *= sc0;
            oacc[j][2] *= sc1; oacc[j][3] *= sc1;
        }

        // ---- O += P V (P hi/lo in regs; V B-frags via ldmatrix.trans) ----
#pragma unroll
        for (int kc = 0; kc < 4; kc++) {
            const int j0 = 2 * kc, j1 = 2 * kc + 1;
            uint32_t pah[4], pal[4];
            {
                float e0, e1;
                pah[0] = cvt2bf(sacc[j0][0], sacc[j0][1]);
                e0 = sacc[j0][0] - __uint_as_float(pah[0] << 16);
                e1 = sacc[j0][1] - __uint_as_float(pah[0] & 0xffff0000u);
                pal[0] = cvt2bf(e0, e1);
                pah[1] = cvt2bf(sacc[j0][2], sacc[j0][3]);
                e0 = sacc[j0][2] - __uint_as_float(pah[1] << 16);
                e1 = sacc[j0][3] - __uint_as_float(pah[1] & 0xffff0000u);
                pal[1] = cvt2bf(e0, e1);
                pah[2] = cvt2bf(sacc[j1][0], sacc[j1][1]);
                e0 = sacc[j1][0] - __uint_as_float(pah[2] << 16);
                e1 = sacc[j1][1] - __uint_as_float(pah[2] & 0xffff0000u);
                pal[2] = cvt2bf(e0, e1);
                pah[3] = cvt2bf(sacc[j1][2], sacc[j1][3]);
                e0 = sacc[j1][2] - __uint_as_float(pah[3] << 16);
                e1 = sacc[j1][3] - __uint_as_float(pah[3] & 0xffff0000u);
                pal[3] = cvt2bf(e0, e1);
            }
#pragma unroll
            for (int np = 0; np < 4; np++) {
                uint32_t vh4[4], vl4[4];
                const uint32_t va = kvb + 18432 +
                    (uint32_t)((kc * 16) * AP) + np * 32 + lane_off;
                ldmx4t(vh4, va);
                ldmx4t(vl4, va + 9216);
#pragma unroll
                for (int o = 0; o < 2; o++) {
                    const int nt = 2 * np + o;
                    mma_bf16(oacc[nt], pah, vh4[2 * o], vh4[2 * o + 1]);
                    mma_bf16(oacc[nt], pah, vl4[2 * o], vl4[2 * o + 1]);
                    mma_bf16(oacc[nt], pal, vh4[2 * o], vh4[2 * o + 1]);
                }
            }
        }

        __syncthreads();   // all warps done reading buf[kt&1]
        if (kt + 2 < SEQ / 64) {
            ISSUE_KV((kt + 2) * 64, KVBUF0 + (kt & 1) * KVSZ);
            CP_COMMIT();
        }
    }

    // ---- normalize + write out[b][q][h*64+dh] ----
    const float inv0 = 1.0f / l0, inv1 = 1.0f / l1;
    const int qa = q0 + w * 16 + gid;
    const int qb = qa + 8;
#pragma unroll
    for (int j = 0; j < 8; j++) {
        const int col = h * DHEAD + 8 * j + 2 * tg;
        float2 v0 = {oacc[j][0] * inv0, oacc[j][1] * inv0};
        float2 v1 = {oacc[j][2] * inv1, oacc[j][3] * inv1};
        *(float2*)(out + ((size_t)bb * SEQ + qa) * DMODEL + col) = v0;
        *(float2*)(out + ((size_t)bb * SEQ + qb) * DMODEL + col) = v1;
    }
}

extern "C" void kernel_launch(void* const* d_in, const int* in_sizes, int n_in,
                              void* d_out, int out_size) {
    const float* x    = (const float*)d_in[0];
    const float* W    = (const float*)d_in[1];
    const float* bias = (const float*)d_in[2];
    float* out = (float*)d_out;

    conv_x<<<(MROWS * DMODEL / 4) / 256, 256>>>(x);
    conv_wT<<<dim3(N3 / 32, DMODEL / 32), dim3(32, 8)>>>(W);

    (void)cudaFuncSetAttribute(gemm_mma,
                               cudaFuncAttributeMaxDynamicSharedMemorySize, GEMM_SMEM);
    gemm_mma<<<dim3(N3 / 128, MROWS / 128), 256, GEMM_SMEM>>>(bias);

    (void)cudaFuncSetAttribute(attn_mma,
                               cudaFuncAttributeMaxDynamicSharedMemorySize, ATTN_SMEM);
    dim3 agrid(SEQ / 128, NHEADS, BATCH);
    attn_mma<<<agrid, 256, ATTN_SMEM>>>(out);
}